// round 17
// baseline (speedup 1.0000x reference)
#include <cuda_runtime.h>
#include <cstdint>

// Problem constants (fixed: B=16, T=1024, D=1024, O=10)
#define BB 16
#define TT 1024
#define DD 1024
#define OO 10

#define CTA 256
#define WARPS 8
#define RPW 4                      // rows per warp
#define RPC 32                     // rows per CTA
#define KT2 256                    // d per stage (1 KB per row)
#define NIT (DD / KT2)             // 4 iterations
#define W_FLOATS (OO * DD)         // 10240 floats = 40 KB
#define STG_FLOATS (RPC * KT2)     // 8192 floats = 32 KB per stage
#define PART_OFF (W_FLOATS + 2 * STG_FLOATS)        // floats: 26624
#define MBAR_OFF ((PART_OFF + 320) * 4)             // bytes: 107776
#define SMEM_BYTES (MBAR_OFF + 32)                  // ~105.3 KB

__device__ float g_scores[BB * OO * TT];   // [b][o][t]
__device__ float g_wx[BB * OO * TT];       // softmaxed, [b][o][i]

// ---------------------------------------------------------------------------
// PTX helpers: 1D bulk-async copy + mbarrier
// ---------------------------------------------------------------------------
__device__ __forceinline__ uint32_t smem_u32(const void* p) {
    return (uint32_t)__cvta_generic_to_shared(p);
}
__device__ __forceinline__ void mbar_init(uint32_t mbar, uint32_t cnt) {
    asm volatile("mbarrier.init.shared.b64 [%0], %1;" :: "r"(mbar), "r"(cnt)
                 : "memory");
}
__device__ __forceinline__ void mbar_expect_tx(uint32_t mbar, uint32_t bytes) {
    asm volatile("mbarrier.arrive.expect_tx.shared.b64 _, [%0], %1;"
                 :: "r"(mbar), "r"(bytes) : "memory");
}
__device__ __forceinline__ void mbar_wait(uint32_t mbar, uint32_t parity) {
    asm volatile(
        "{\n\t"
        ".reg .pred P;\n\t"
        "WAIT_%=:\n\t"
        "mbarrier.try_wait.parity.shared.b64 P, [%0], %1;\n\t"
        "@P bra.uni DONE_%=;\n\t"
        "bra.uni WAIT_%=;\n\t"
        "DONE_%=:\n\t"
        "}"
        :: "r"(mbar), "r"(parity) : "memory");
}
__device__ __forceinline__ void bulk_cp(uint32_t dst_smem, const void* src,
                                        uint32_t bytes, uint32_t mbar) {
    asm volatile(
        "cp.async.bulk.shared::cluster.global.mbarrier::complete_tx::bytes "
        "[%0], [%1], %2, [%3];"
        :: "r"(dst_smem), "l"(src), "r"(bytes), "r"(mbar) : "memory");
}

// ---------------------------------------------------------------------------
// Shared GEMV pass: 32 rows x 1024 d per CTA, logits via bulk-async stages,
// W (10 x 1024) in smem. acc[4][10] scalar.
// ---------------------------------------------------------------------------
__device__ __forceinline__ void gemv_tma(const float* __restrict__ rows_base,
                                         const float* __restrict__ Wsrc,
                                         float* smem,
                                         float (&acc)[RPW][OO]) {
    const int tid = threadIdx.x;
    const int warp = tid >> 5;
    const int lane = tid & 31;

    float* Wsm = smem;
    float* stg = smem + W_FLOATS;
    const uint32_t stg_u = smem_u32(stg);
    const uint32_t mbar0 = smem_u32((char*)smem + MBAR_OFF);
    const uint32_t mbar1 = mbar0 + 8;

    if (tid == 0) {
        mbar_init(mbar0, 1);
        mbar_init(mbar1, 1);
        // make init visible to the async proxy before first bulk copy
        asm volatile("fence.proxy.async.shared::cta;" ::: "memory");
        // prologue: issue stages 0 and 1
        #pragma unroll
        for (int s = 0; s < 2; s++) {
            const uint32_t mb = s ? mbar1 : mbar0;
            mbar_expect_tx(mb, STG_FLOATS * 4);
            #pragma unroll 4
            for (int r = 0; r < RPC; r++)
                bulk_cp(stg_u + (uint32_t)(s * STG_FLOATS + r * KT2) * 4,
                        rows_base + (size_t)r * DD + s * KT2,
                        KT2 * 4, mb);
        }
    }

    // W -> smem (overlaps the bulk copies)
    {
        const float4* Wv = (const float4*)Wsrc;
        float4* Ws = (float4*)Wsm;
        #pragma unroll
        for (int t = 0; t < 10; t++)
            Ws[tid + t * CTA] = Wv[tid + t * CTA];
    }
    __syncthreads();   // W ready; mbarrier inits visible to all threads

    #pragma unroll
    for (int r = 0; r < RPW; r++)
        #pragma unroll
        for (int o = 0; o < OO; o++) acc[r][o] = 0.0f;

    const float* myrow = stg + (warp * RPW) * KT2 + lane * 4;
    const float* wlane = Wsm + lane * 4;

    #pragma unroll
    for (int it = 0; it < NIT; it++) {
        const int slot = it & 1;
        mbar_wait(slot ? mbar1 : mbar0, (it >> 1) & 1);

        const float* sb = myrow + slot * STG_FLOATS;
        const float* wb = wlane + it * KT2;

        #pragma unroll
        for (int j = 0; j < 2; j++) {
            float4 v[RPW];
            #pragma unroll
            for (int r = 0; r < RPW; r++)
                v[r] = *(const float4*)(sb + r * KT2 + j * 128);
            #pragma unroll
            for (int o = 0; o < OO; o++) {
                const float4 w4 = *(const float4*)(wb + o * DD + j * 128);
                #pragma unroll
                for (int r = 0; r < RPW; r++) {
                    acc[r][o] = fmaf(v[r].x, w4.x, acc[r][o]);
                    acc[r][o] = fmaf(v[r].y, w4.y, acc[r][o]);
                    acc[r][o] = fmaf(v[r].z, w4.z, acc[r][o]);
                    acc[r][o] = fmaf(v[r].w, w4.w, acc[r][o]);
                }
            }
        }

        __syncthreads();   // slot fully consumed
        if (tid == 0 && it + 2 < NIT) {
            const uint32_t mb = slot ? mbar1 : mbar0;
            mbar_expect_tx(mb, STG_FLOATS * 4);
            #pragma unroll 4
            for (int r = 0; r < RPC; r++)
                bulk_cp(stg_u + (uint32_t)(slot * STG_FLOATS + r * KT2) * 4,
                        rows_base + (size_t)r * DD + (it + 2) * KT2,
                        KT2 * 4, mb);
        }
    }
}

// Shared epilogue: warp-reduce 40 partials, combine via smem, write [o][t].
__device__ __forceinline__ void epilogue(float (&acc)[RPW][OO], float* smem,
                                         int row0blk, float* __restrict__ dst,
                                         float scale,
                                         const float* __restrict__ bias) {
    float (*partial)[40] = (float (*)[40])(smem + PART_OFF);
    const int warp = threadIdx.x >> 5;
    const int lane = threadIdx.x & 31;

    #pragma unroll
    for (int r = 0; r < RPW; r++)
        #pragma unroll
        for (int o = 0; o < OO; o++) {
            float x = acc[r][o];
            #pragma unroll
            for (int s = 16; s > 0; s >>= 1)
                x += __shfl_xor_sync(0xffffffffu, x, s);
            if (lane == 0) partial[warp][r * OO + o] = x;
        }
    __syncthreads();

    // 320 results = 8 warps x 40; threads 0..255 cover 256, warps reloop
    for (int i = threadIdx.x; i < WARPS * 40; i += CTA) {
        const int w = i / 40, idx = i % 40;
        const int r = idx / OO, o = idx % OO;
        float v = partial[w][idx];
        const int row = row0blk + w * RPW + r;
        const int t = row % TT;
        if (bias) v = (v + __ldg(&bias[o])) * scale;
        dst[o * TT + t] = v;
    }
}

// ---------------------------------------------------------------------------
// Kernel 1: scores[b][o][t] = (logits[b,t,:] . W[o,:] + bias[o]) / OO
// ---------------------------------------------------------------------------
__global__ __launch_bounds__(CTA) void k_scores(const float* __restrict__ logits,
                                                const float* __restrict__ W,
                                                const float* __restrict__ bias) {
    extern __shared__ float smem[];
    const int row0blk = blockIdx.x * RPC;
    const int b = row0blk / TT;

    float acc[RPW][OO];
    gemv_tma(logits + (size_t)row0blk * DD, W, smem, acc);
    epilogue(acc, smem, row0blk, g_scores + b * OO * TT, 1.0f / OO, bias);
}

// ---------------------------------------------------------------------------
// Kernel 2: softmax over t for each (b,o). 160 blocks x 256 threads.
// ---------------------------------------------------------------------------
__global__ __launch_bounds__(256) void k_softmax() {
    const int ro = blockIdx.x;
    const int tid = threadIdx.x;
    const float4 v = ((const float4*)&g_scores[ro * TT])[tid];

    __shared__ float red[8];

    float m = fmaxf(fmaxf(v.x, v.y), fmaxf(v.z, v.w));
    #pragma unroll
    for (int s = 16; s > 0; s >>= 1)
        m = fmaxf(m, __shfl_xor_sync(0xffffffffu, m, s));
    if ((tid & 31) == 0) red[tid >> 5] = m;
    __syncthreads();
    float mall = red[0];
    #pragma unroll
    for (int i = 1; i < 8; i++) mall = fmaxf(mall, red[i]);
    __syncthreads();

    float4 e;
    e.x = __expf(v.x - mall);
    e.y = __expf(v.y - mall);
    e.z = __expf(v.z - mall);
    e.w = __expf(v.w - mall);
    float s4 = e.x + e.y + e.z + e.w;
    #pragma unroll
    for (int s = 16; s > 0; s >>= 1)
        s4 += __shfl_xor_sync(0xffffffffu, s4, s);
    if ((tid & 31) == 0) red[tid >> 5] = s4;
    __syncthreads();
    float sall = 0.0f;
    #pragma unroll
    for (int i = 0; i < 8; i++) sall += red[i];

    const float inv = 1.0f / sall;
    float4 w;
    w.x = e.x * inv; w.y = e.y * inv; w.z = e.z * inv; w.w = e.w * inv;
    ((float4*)&g_wx[ro * TT])[tid] = w;
}

// ---------------------------------------------------------------------------
// Kernel 3: out[b][o][t] = sum_i logits[b,t,i] * g_wx[b][o][i]
// ---------------------------------------------------------------------------
__global__ __launch_bounds__(CTA) void k_out(const float* __restrict__ logits,
                                             float* __restrict__ out) {
    extern __shared__ float smem[];
    const int row0blk = blockIdx.x * RPC;
    const int b = row0blk / TT;               // 32 rows never cross a batch

    float acc[RPW][OO];
    gemv_tma(logits + (size_t)row0blk * DD, g_wx + (size_t)b * W_FLOATS,
             smem, acc);
    epilogue(acc, smem, row0blk, out + b * OO * TT, 1.0f, nullptr);
}

// ---------------------------------------------------------------------------
// Launch: inputs per metadata order: logits, decision(unused), W, b
// ---------------------------------------------------------------------------
extern "C" void kernel_launch(void* const* d_in, const int* in_sizes, int n_in,
                              void* d_out, int out_size) {
    const float* logits = (const float*)d_in[0];
    const float* W = (const float*)d_in[2];
    const float* bias = (const float*)d_in[3];
    float* out = (float*)d_out;

    cudaFuncSetAttribute(k_scores, cudaFuncAttributeMaxDynamicSharedMemorySize,
                         SMEM_BYTES);
    cudaFuncSetAttribute(k_out, cudaFuncAttributeMaxDynamicSharedMemorySize,
                         SMEM_BYTES);

    k_scores<<<(BB * TT) / RPC, CTA, SMEM_BYTES>>>(logits, W, bias);
    k_softmax<<<BB * OO, 256>>>();
    k_out<<<(BB * TT) / RPC, CTA, SMEM_BYTES>>>(logits, out);
}